// round 1
// baseline (speedup 1.0000x reference)
#include <cuda_runtime.h>
#include <cstdint>

typedef unsigned long long u64;
typedef unsigned int u32;

#define BMAX 8
#define NPROP 4000
#define NCLS 91
#define NC1 90
#define CAP 81920
#define KPRE 2048
#define SCORE_TH 0.05f
#define NMS_TH 0.5f
#define XFORM_CLIP 4.135166556742356f
#define DETS 100

__device__ int g_cnt[BMAX];
__device__ u64 g_keys[BMAX][CAP];
__device__ u64 g_sorted[BMAX][KPRE];
__device__ float4 g_box[BMAX][KPRE];
__device__ float4 g_obox[BMAX][KPRE];
__device__ float g_score[BMAX][KPRE];
__device__ int g_label[BMAX][KPRE];
__device__ u64 g_sup[BMAX][KPRE][32];

__device__ __forceinline__ float read_dim(const void* p) {
    // scalar may arrive as int32/int64 (little-endian) or float32
    int v = *(const int*)p;
    if (v > 0 && v < 1000000) return (float)v;
    return *(const float*)p;
}

__global__ void k_init(int B) {
    int t = threadIdx.x;
    if (t < B) g_cnt[t] = 0;
}

// One warp per proposal row: softmax over 91 logits, then per-class score
// threshold, decode, validity check, emit 64-bit sortable key.
__global__ void k_cand(const float* __restrict__ logits,
                       const float* __restrict__ reg,
                       const float* __restrict__ props,
                       const void* __restrict__ p_h,
                       const void* __restrict__ p_w,
                       int B) {
    int wid = threadIdx.x >> 5, lane = threadIdx.x & 31;
    int row = blockIdx.x * 4 + wid;
    if (row >= B * NPROP) return;
    int b = row / NPROP;
    int n = row - b * NPROP;

    const float* lr = logits + (size_t)row * NCLS;
    float l0 = lr[lane];
    float l1 = lr[lane + 32];
    float l2 = (lane < NCLS - 64) ? lr[lane + 64] : -3.0e38f;

    float m = fmaxf(fmaxf(l0, l1), l2);
    #pragma unroll
    for (int o = 16; o; o >>= 1) m = fmaxf(m, __shfl_xor_sync(~0u, m, o));

    float e0 = expf(l0 - m);
    float e1 = expf(l1 - m);
    float e2 = (lane < NCLS - 64) ? expf(l2 - m) : 0.0f;
    float sum = e0 + e1 + e2;
    #pragma unroll
    for (int o = 16; o; o >>= 1) sum += __shfl_xor_sync(~0u, sum, o);

    float img_h = read_dim(p_h);
    float img_w = read_dim(p_w);

    float4 pr = *(const float4*)(props + (size_t)row * 4);
    float pwd = pr.z - pr.x, pht = pr.w - pr.y;
    float cx = pr.x + 0.5f * pwd, cy = pr.y + 0.5f * pht;

    #pragma unroll
    for (int slot = 0; slot < 3; slot++) {
        int p = lane + 32 * slot;
        if (p < 1 || p >= NCLS) continue;
        float e = (slot == 0) ? e0 : (slot == 1 ? e1 : e2);
        float s = e / sum;
        if (s > SCORE_TH) {
            float4 rg = *(const float4*)(reg + (size_t)row * 4 * NCLS + 4 * p);
            float dx = rg.x / 10.0f, dy = rg.y / 10.0f;
            float dw = fminf(rg.z / 5.0f, XFORM_CLIP);
            float dh = fminf(rg.w / 5.0f, XFORM_CLIP);
            float pcx = dx * pwd + cx, pcy = dy * pht + cy;
            float bw = expf(dw) * pwd, bh = expf(dh) * pht;
            float x1 = fminf(fmaxf(pcx - 0.5f * bw, 0.0f), img_w);
            float y1 = fminf(fmaxf(pcy - 0.5f * bh, 0.0f), img_h);
            float x2 = fminf(fmaxf(pcx + 0.5f * bw, 0.0f), img_w);
            float y2 = fminf(fmaxf(pcy + 0.5f * bh, 0.0f), img_h);
            if ((x2 - x1 >= 1.0f) && (y2 - y1 >= 1.0f)) {
                u32 sb = __float_as_uint(s);
                u32 mf = (u32)(n * NC1 + (p - 1));
                u64 key = ((u64)(sb ^ 0xFFFFFFFFu) << 32) | (u64)mf;
                int idx = atomicAdd(&g_cnt[b], 1);
                if (idx < CAP) g_keys[b][idx] = key;
            }
        }
    }
}

// One block (1024 thr) per image: MSB radix-select rank-2048 key, collect,
// bitonic sort 2048 keys ascending (== descending score, index tiebreak).
__global__ void k_select(int B) {
    int b = blockIdx.x;
    if (b >= B) return;
    __shared__ u64 sh_list[KPRE];
    __shared__ int sh_hist[256];
    __shared__ u64 sh_prefix;
    __shared__ int sh_rem;
    __shared__ int sh_c2;
    int tid = threadIdx.x;
    const int T = 1024;

    int cnt = g_cnt[b];
    if (cnt > CAP) cnt = CAP;
    u64 thresh = ~0ull;

    if (cnt > KPRE) {
        if (tid == 0) { sh_prefix = 0ull; sh_rem = KPRE; }
        __syncthreads();
        for (int shift = 56; shift >= 0; shift -= 8) {
            for (int t = tid; t < 256; t += T) sh_hist[t] = 0;
            __syncthreads();
            u64 prefix = sh_prefix;
            u64 hm = (shift == 56) ? 0ull : (~0ull << (shift + 8));
            for (int i = tid; i < cnt; i += T) {
                u64 k = g_keys[b][i];
                if ((k & hm) == prefix)
                    atomicAdd(&sh_hist[(int)((k >> shift) & 0xFF)], 1);
            }
            __syncthreads();
            if (tid == 0) {
                int rem = sh_rem;
                for (int t2 = 0; t2 < 256; t2++) {
                    int c = sh_hist[t2];
                    if (rem > c) rem -= c;
                    else { sh_prefix = prefix | ((u64)t2 << shift); break; }
                }
                sh_rem = rem;
            }
            __syncthreads();
        }
        thresh = sh_prefix;
    }

    if (tid == 0) sh_c2 = 0;
    __syncthreads();
    for (int i = tid; i < cnt; i += T) {
        u64 k = g_keys[b][i];
        if (k <= thresh) {
            int pos = atomicAdd(&sh_c2, 1);
            if (pos < KPRE) sh_list[pos] = k;
        }
    }
    __syncthreads();
    int got = sh_c2; if (got > KPRE) got = KPRE;
    for (int t = got + tid; t < KPRE; t += T) sh_list[t] = ~0ull;
    __syncthreads();

    for (int size = 2; size <= KPRE; size <<= 1) {
        for (int stride = size >> 1; stride > 0; stride >>= 1) {
            int t = tid;
            int i = ((t & ~(stride - 1)) << 1) | (t & (stride - 1));
            int j = i + stride;
            bool asc = (i & size) == 0;
            u64 a = sh_list[i], c = sh_list[j];
            if ((a > c) == asc) { sh_list[i] = c; sh_list[j] = a; }
            __syncthreads();
        }
    }
    for (int t = tid; t < KPRE; t += T) g_sorted[b][t] = sh_list[t];
}

// One block (256 thr) per image: decode boxes for selected 2048, compute
// max coordinate (for the class-offset trick), build offset boxes.
__global__ void k_decode(const float* __restrict__ reg,
                         const float* __restrict__ props,
                         const void* __restrict__ p_h,
                         const void* __restrict__ p_w,
                         int B) {
    int b = blockIdx.x;
    if (b >= B) return;
    __shared__ float sh_max[256];
    float img_h = read_dim(p_h);
    float img_w = read_dim(p_w);
    float lmax = 0.0f;
    for (int s = threadIdx.x; s < KPRE; s += 256) {
        u64 k = g_sorted[b][s];
        float4 bx = make_float4(0.f, 0.f, 0.f, 0.f);
        float sc = -1.0f;
        int lab = 0;
        if (k != ~0ull) {
            u32 mf = (u32)(k & 0xFFFFFFFFu);
            sc = __uint_as_float(~((u32)(k >> 32)));
            int n = (int)(mf / NC1);
            int p = (int)(mf - (u32)n * NC1) + 1;
            int row = b * NPROP + n;
            float4 pr = *(const float4*)(props + (size_t)row * 4);
            float pwd = pr.z - pr.x, pht = pr.w - pr.y;
            float cx = pr.x + 0.5f * pwd, cy = pr.y + 0.5f * pht;
            float4 rg = *(const float4*)(reg + (size_t)row * 4 * NCLS + 4 * p);
            float dx = rg.x / 10.0f, dy = rg.y / 10.0f;
            float dw = fminf(rg.z / 5.0f, XFORM_CLIP);
            float dh = fminf(rg.w / 5.0f, XFORM_CLIP);
            float pcx = dx * pwd + cx, pcy = dy * pht + cy;
            float bw = expf(dw) * pwd, bh = expf(dh) * pht;
            bx.x = fminf(fmaxf(pcx - 0.5f * bw, 0.0f), img_w);
            bx.y = fminf(fmaxf(pcy - 0.5f * bh, 0.0f), img_h);
            bx.z = fminf(fmaxf(pcx + 0.5f * bw, 0.0f), img_w);
            bx.w = fminf(fmaxf(pcy + 0.5f * bh, 0.0f), img_h);
            lab = p;
            lmax = fmaxf(lmax, fmaxf(fmaxf(bx.x, bx.y), fmaxf(bx.z, bx.w)));
        }
        g_box[b][s] = bx;
        g_score[b][s] = sc;
        g_label[b][s] = lab;
    }
    sh_max[threadIdx.x] = lmax;
    __syncthreads();
    for (int o = 128; o; o >>= 1) {
        if (threadIdx.x < o)
            sh_max[threadIdx.x] = fmaxf(sh_max[threadIdx.x], sh_max[threadIdx.x + o]);
        __syncthreads();
    }
    float mc = sh_max[0];
    for (int s = threadIdx.x; s < KPRE; s += 256) {
        float4 bx = g_box[b][s];
        float off = (float)g_label[b][s] * (mc + 1.0f);
        g_obox[b][s] = make_float4(bx.x + off, bx.y + off, bx.z + off, bx.w + off);
    }
}

// 64x64 tile suppression bitmask: sup[i] bit j set iff IoU(i,j)>0.5 and j>i.
__global__ void k_sup(int B) {
    int b = blockIdx.z;
    int ct = blockIdx.x, rt = blockIdx.y;
    int t = threadIdx.x;  // 64
    __shared__ float4 cb[64];
    cb[t] = g_obox[b][ct * 64 + t];
    __syncthreads();
    int i = rt * 64 + t;
    float4 bi = g_obox[b][i];
    float ai = (bi.z - bi.x) * (bi.w - bi.y);
    u64 mask = 0ull;
    #pragma unroll 4
    for (int j = 0; j < 64; j++) {
        int jg = ct * 64 + j;
        float4 bj = cb[j];
        float ltx = fmaxf(bi.x, bj.x), lty = fmaxf(bi.y, bj.y);
        float rbx = fminf(bi.z, bj.z), rby = fminf(bi.w, bj.w);
        float w = fmaxf(rbx - ltx, 0.0f), h = fmaxf(rby - lty, 0.0f);
        float inter = w * h;
        float aj = (bj.z - bj.x) * (bj.w - bj.y);
        float iou = inter / (ai + aj - inter);
        if ((iou > NMS_TH) && (jg > i)) mask |= (1ull << j);
    }
    g_sup[b][i][ct] = mask;
}

// One block (1024 thr) per image: Jacobi fixpoint of
// kept[i] = valid[i] & !exists j<i: kept[j] & sup(j,i)  == sequential greedy NMS.
// Then emit first 100 kept entries in sorted order.
__global__ void k_nms_out(float* __restrict__ out, int B) {
    int b = blockIdx.x;
    if (b >= B) return;
    int tid = threadIdx.x, lane = tid & 31, wid = tid >> 5;  // 32 warps
    __shared__ u64 sh_kept[32], sh_valid[32];
    __shared__ u64 part[32][33];
    __shared__ int sh_changed;

    {
        int s0 = wid * 64 + lane;
        u32 b0 = __ballot_sync(~0u, g_score[b][s0] > SCORE_TH);
        u32 b1 = __ballot_sync(~0u, g_score[b][s0 + 32] > SCORE_TH);
        if (lane == 0) {
            u64 v = ((u64)b1 << 32) | (u64)b0;
            sh_valid[wid] = v;
            sh_kept[wid] = v;
        }
    }
    __syncthreads();

    while (true) {
        u64 acc = 0ull;
        for (int r = wid; r < KPRE; r += 32) {
            if ((sh_kept[r >> 6] >> (r & 63)) & 1ull)
                acc |= g_sup[b][r][lane];
        }
        part[wid][lane] = acc;
        if (tid == 0) sh_changed = 0;
        __syncthreads();
        u64 v = part[lane][wid];
        #pragma unroll
        for (int o = 16; o; o >>= 1) v |= __shfl_xor_sync(~0u, v, o);
        u64 oldk = sh_kept[wid];
        u64 nk = sh_valid[wid] & ~v;
        __syncthreads();
        if (lane == 0) {
            sh_kept[wid] = nk;
            if (nk != oldk) sh_changed = 1;
        }
        __syncthreads();
        if (!sh_changed) break;
    }

    // defaults: boxes 0, scores 0, labels -1
    const int soff = B * DETS * 4;
    const int loff = B * DETS * 4 + B * DETS;
    for (int i = tid; i < DETS; i += 1024) {
        float* bo = out + (size_t)(b * DETS + i) * 4;
        bo[0] = 0.f; bo[1] = 0.f; bo[2] = 0.f; bo[3] = 0.f;
        out[soff + b * DETS + i] = 0.f;
        out[loff + b * DETS + i] = -1.f;
    }
    __syncthreads();

    if (wid == 0) {
        int base = 0;
        for (int w = 0; w < 32 && base < DETS; w++) {
            u64 word = sh_kept[w];
            u32 lo = (u32)word;
            u32 hi = (u32)(word >> 32);
            {
                u32 myb = (lo >> lane) & 1u;
                int pre = __popc(lo & ((1u << lane) - 1u));
                int rank = base + pre;
                if (myb && rank < DETS) {
                    int s = w * 64 + lane;
                    float4 bx = g_box[b][s];
                    float* bo = out + (size_t)(b * DETS + rank) * 4;
                    bo[0] = bx.x; bo[1] = bx.y; bo[2] = bx.z; bo[3] = bx.w;
                    out[soff + b * DETS + rank] = g_score[b][s];
                    out[loff + b * DETS + rank] = (float)g_label[b][s];
                }
                base += __popc(lo);
            }
            {
                u32 myb = (hi >> lane) & 1u;
                int pre = __popc(hi & ((1u << lane) - 1u));
                int rank = base + pre;
                if (myb && rank < DETS) {
                    int s = w * 64 + 32 + lane;
                    float4 bx = g_box[b][s];
                    float* bo = out + (size_t)(b * DETS + rank) * 4;
                    bo[0] = bx.x; bo[1] = bx.y; bo[2] = bx.z; bo[3] = bx.w;
                    out[soff + b * DETS + rank] = g_score[b][s];
                    out[loff + b * DETS + rank] = (float)g_label[b][s];
                }
                base += __popc(hi);
            }
        }
    }
}

extern "C" void kernel_launch(void* const* d_in, const int* in_sizes, int n_in,
                              void* d_out, int out_size) {
    const float* logits = (const float*)d_in[0];
    const float* reg = (const float*)d_in[1];
    const float* props = (const float*)d_in[2];
    const void* p_h = d_in[3];
    const void* p_w = d_in[4];
    float* out = (float*)d_out;

    int B = in_sizes[0] / (NPROP * NCLS);
    if (B < 1) B = 1;
    if (B > BMAX) B = BMAX;

    k_init<<<1, 32>>>(B);
    int rows = B * NPROP;
    k_cand<<<(rows + 3) / 4, 128>>>(logits, reg, props, p_h, p_w, B);
    k_select<<<B, 1024>>>(B);
    k_decode<<<B, 256>>>(reg, props, p_h, p_w, B);
    dim3 gs(KPRE / 64, KPRE / 64, B);
    k_sup<<<gs, 64>>>(B);
    k_nms_out<<<B, 1024>>>(out, B);
}

// round 2
// speedup vs baseline: 1.5346x; 1.5346x over previous
#include <cuda_runtime.h>
#include <cstdint>

typedef unsigned long long u64;
typedef unsigned int u32;

#define BMAX 8
#define NPROP 4000
#define NCLS 91
#define NC1 90
#define CAP 81920
#define SHCAP 16384
#define KPRE 2048
#define SCORE_TH 0.05f
#define NMS_TH 0.5f
#define XFORM_CLIP 4.135166556742356f
#define DETS 100

__device__ int g_cnt[BMAX];                 // zero-initialized at load; reset by k_nms_out
__device__ u64 g_keys[BMAX][CAP];
__device__ float4 g_box[BMAX][KPRE];
__device__ float4 g_obox[BMAX][KPRE];
__device__ float g_score[BMAX][KPRE];
__device__ int g_label[BMAX][KPRE];
__device__ u64 g_sup[BMAX][KPRE][32];

__device__ __forceinline__ float read_dim(const void* p) {
    int v = *(const int*)p;
    if (v > 0 && v < 1000000) return (float)v;
    return *(const float*)p;
}

// FMA-pipe exp (avoids MUFU.EX2 throughput floor). rel err ~2e-6.
__device__ __forceinline__ float fexp(float x) {
    float t = x * 1.4426950408889634f;
    t = fmaxf(t, -126.0f);
    float k = rintf(t);
    float f = t - k;
    float p = 1.3333558146e-3f;
    p = fmaf(p, f, 9.6181291077e-3f);
    p = fmaf(p, f, 5.5504108664e-2f);
    p = fmaf(p, f, 2.4022650695e-1f);
    p = fmaf(p, f, 6.9314718056e-1f);
    p = fmaf(p, f, 1.0f);
    float s = __int_as_float(((int)k + 127) << 23);
    return p * s;
}

// One warp per proposal row: softmax over 91 logits, threshold, decode-check,
// emit 64-bit sortable key (inverted score bits | flat index).
__global__ void k_cand(const float* __restrict__ logits,
                       const float* __restrict__ reg,
                       const float* __restrict__ props,
                       const void* __restrict__ p_h,
                       const void* __restrict__ p_w,
                       int B) {
    int wid = threadIdx.x >> 5, lane = threadIdx.x & 31;
    int row = blockIdx.x * 8 + wid;
    if (row >= B * NPROP) return;
    int b = row / NPROP;
    int n = row - b * NPROP;

    const float* lr = logits + (size_t)row * NCLS;
    float l0 = lr[lane];
    float l1 = lr[lane + 32];
    float l2 = (lane < NCLS - 64) ? lr[lane + 64] : -3.0e38f;

    float m = fmaxf(fmaxf(l0, l1), l2);
    #pragma unroll
    for (int o = 16; o; o >>= 1) m = fmaxf(m, __shfl_xor_sync(~0u, m, o));

    float e0 = fexp(l0 - m);
    float e1 = fexp(l1 - m);
    float e2 = (lane < NCLS - 64) ? fexp(l2 - m) : 0.0f;
    float sum = e0 + e1 + e2;
    #pragma unroll
    for (int o = 16; o; o >>= 1) sum += __shfl_xor_sync(~0u, sum, o);
    float inv = 1.0f / sum;

    float img_h = read_dim(p_h);
    float img_w = read_dim(p_w);

    float4 pr = *(const float4*)(props + (size_t)row * 4);
    float pwd = pr.z - pr.x, pht = pr.w - pr.y;
    float cx = pr.x + 0.5f * pwd, cy = pr.y + 0.5f * pht;

    #pragma unroll
    for (int slot = 0; slot < 3; slot++) {
        int p = lane + 32 * slot;
        if (p < 1 || p >= NCLS) continue;
        float e = (slot == 0) ? e0 : (slot == 1 ? e1 : e2);
        float s = e * inv;
        if (s > SCORE_TH) {
            float4 rg = *(const float4*)(reg + (size_t)row * 4 * NCLS + 4 * p);
            float dx = rg.x / 10.0f, dy = rg.y / 10.0f;
            float dw = fminf(rg.z / 5.0f, XFORM_CLIP);
            float dh = fminf(rg.w / 5.0f, XFORM_CLIP);
            float pcx = dx * pwd + cx, pcy = dy * pht + cy;
            float bw = expf(dw) * pwd, bh = expf(dh) * pht;
            float x1 = fminf(fmaxf(pcx - 0.5f * bw, 0.0f), img_w);
            float y1 = fminf(fmaxf(pcy - 0.5f * bh, 0.0f), img_h);
            float x2 = fminf(fmaxf(pcx + 0.5f * bw, 0.0f), img_w);
            float y2 = fminf(fmaxf(pcy + 0.5f * bh, 0.0f), img_h);
            if ((x2 - x1 >= 1.0f) && (y2 - y1 >= 1.0f)) {
                u32 sb = __float_as_uint(s);
                u32 mf = (u32)(n * NC1 + (p - 1));
                u64 key = ((u64)(sb ^ 0xFFFFFFFFu) << 32) | (u64)mf;
                int idx = atomicAdd(&g_cnt[b], 1);
                if (idx < CAP) g_keys[b][idx] = key;
            }
        }
    }
}

// One block (1024 thr) per image: shared-resident radix-select rank-2048 key,
// collect, bitonic sort, then fused decode (+class-offset boxes).
extern __shared__ u64 dyn_keys[];
__global__ void k_select(const float* __restrict__ reg,
                         const float* __restrict__ props,
                         const void* __restrict__ p_h,
                         const void* __restrict__ p_w,
                         int B) {
    int b = blockIdx.x;
    __shared__ u64 sh_list[KPRE];
    __shared__ int sh_hist[256];
    __shared__ int sh_pref[256];
    __shared__ u64 sh_prefix;
    __shared__ int sh_rem;
    __shared__ int sh_c2;
    __shared__ float sh_red[32];
    int tid = threadIdx.x;
    const int T = 1024;

    int cnt = g_cnt[b];
    if (cnt > CAP) cnt = CAP;
    bool use_sh = (cnt <= SHCAP);
    const u64* keys = use_sh ? (const u64*)dyn_keys : (const u64*)g_keys[b];
    if (use_sh) {
        for (int i = tid; i < cnt; i += T) dyn_keys[i] = g_keys[b][i];
    }
    __syncthreads();

    u64 thresh = ~0ull;
    if (cnt > KPRE) {
        if (tid == 0) { sh_prefix = 0ull; sh_rem = KPRE; }
        __syncthreads();
        for (int shift = 56; shift >= 0; shift -= 8) {
            if (tid < 256) sh_hist[tid] = 0;
            __syncthreads();
            u64 prefix = sh_prefix;
            u64 hm = (shift == 56) ? 0ull : (~0ull << (shift + 8));
            for (int i = tid; i < cnt; i += T) {
                u64 k = keys[i];
                if ((k & hm) == prefix)
                    atomicAdd(&sh_hist[(int)((k >> shift) & 0xFF)], 1);
            }
            __syncthreads();
            // inclusive prefix scan over 256 bins
            if (tid < 256) sh_pref[tid] = sh_hist[tid];
            __syncthreads();
            for (int o = 1; o < 256; o <<= 1) {
                int v = 0;
                if (tid < 256 && tid >= o) v = sh_pref[tid - o];
                __syncthreads();
                if (tid < 256 && tid >= o) sh_pref[tid] += v;
                __syncthreads();
            }
            int rem = sh_rem;
            int excl = 0, incl = 0;
            if (tid < 256) { incl = sh_pref[tid]; excl = incl - sh_hist[tid]; }
            __syncthreads();
            if (tid < 256 && excl < rem && rem <= incl) {
                sh_prefix = prefix | ((u64)tid << shift);
                sh_rem = rem - excl;
            }
            __syncthreads();
        }
        thresh = sh_prefix;
    }

    if (tid == 0) sh_c2 = 0;
    __syncthreads();
    for (int i = tid; i < cnt; i += T) {
        u64 k = keys[i];
        if (k <= thresh) {
            int pos = atomicAdd(&sh_c2, 1);
            if (pos < KPRE) sh_list[pos] = k;
        }
    }
    __syncthreads();
    int got = sh_c2; if (got > KPRE) got = KPRE;
    for (int t = got + tid; t < KPRE; t += T) sh_list[t] = ~0ull;
    __syncthreads();

    // bitonic sort 2048 ascending (== score desc, flat-index asc on ties)
    for (int size = 2; size <= KPRE; size <<= 1) {
        for (int stride = size >> 1; stride > 0; stride >>= 1) {
            int i = ((tid & ~(stride - 1)) << 1) | (tid & (stride - 1));
            int j = i + stride;
            bool asc = (i & size) == 0;
            u64 a = sh_list[i], c = sh_list[j];
            if ((a > c) == asc) { sh_list[i] = c; sh_list[j] = a; }
            __syncthreads();
        }
    }

    // fused decode
    float img_h = read_dim(p_h);
    float img_w = read_dim(p_w);
    float lmax = 0.0f;
    for (int s = tid; s < KPRE; s += T) {
        u64 k = sh_list[s];
        float4 bx = make_float4(0.f, 0.f, 0.f, 0.f);
        float sc = -1.0f;
        int lab = 0;
        if (k != ~0ull) {
            u32 mf = (u32)(k & 0xFFFFFFFFu);
            sc = __uint_as_float(~((u32)(k >> 32)));
            int n = (int)(mf / NC1);
            int p = (int)(mf - (u32)n * NC1) + 1;
            int row = b * NPROP + n;
            float4 pr = *(const float4*)(props + (size_t)row * 4);
            float pwd = pr.z - pr.x, pht = pr.w - pr.y;
            float cx = pr.x + 0.5f * pwd, cy = pr.y + 0.5f * pht;
            float4 rg = *(const float4*)(reg + (size_t)row * 4 * NCLS + 4 * p);
            float dx = rg.x / 10.0f, dy = rg.y / 10.0f;
            float dw = fminf(rg.z / 5.0f, XFORM_CLIP);
            float dh = fminf(rg.w / 5.0f, XFORM_CLIP);
            float pcx = dx * pwd + cx, pcy = dy * pht + cy;
            float bw = expf(dw) * pwd, bh = expf(dh) * pht;
            bx.x = fminf(fmaxf(pcx - 0.5f * bw, 0.0f), img_w);
            bx.y = fminf(fmaxf(pcy - 0.5f * bh, 0.0f), img_h);
            bx.z = fminf(fmaxf(pcx + 0.5f * bw, 0.0f), img_w);
            bx.w = fminf(fmaxf(pcy + 0.5f * bh, 0.0f), img_h);
            lab = p;
            lmax = fmaxf(lmax, fmaxf(fmaxf(bx.x, bx.y), fmaxf(bx.z, bx.w)));
        }
        g_box[b][s] = bx;
        g_score[b][s] = sc;
        g_label[b][s] = lab;
    }
    // block max reduce (for class-offset trick, byte-compatible with reference)
    #pragma unroll
    for (int o = 16; o; o >>= 1) lmax = fmaxf(lmax, __shfl_xor_sync(~0u, lmax, o));
    if ((tid & 31) == 0) sh_red[tid >> 5] = lmax;
    __syncthreads();
    if (tid < 32) {
        float v = sh_red[tid];
        #pragma unroll
        for (int o = 16; o; o >>= 1) v = fmaxf(v, __shfl_xor_sync(~0u, v, o));
        if (tid == 0) sh_red[0] = v;
    }
    __syncthreads();
    float mc = sh_red[0];
    for (int s = tid; s < KPRE; s += T) {
        float4 bx = g_box[b][s];
        float off = (float)g_label[b][s] * (mc + 1.0f);
        g_obox[b][s] = make_float4(bx.x + off, bx.y + off, bx.z + off, bx.w + off);
    }
}

// Upper-triangle suppression bitmask: 256 rows x 64 cols per block.
__global__ void k_sup(int B) {
    int b = blockIdx.z;
    int ct = blockIdx.x;
    int rb = blockIdx.y * 256;
    if (ct < (rb >> 6)) return;  // entire block below diagonal
    __shared__ float4 cb[64];
    __shared__ float ca[64];
    int t = threadIdx.x;
    if (t < 64) {
        float4 bj = g_obox[b][ct * 64 + t];
        cb[t] = bj;
        ca[t] = (bj.z - bj.x) * (bj.w - bj.y);
    }
    __syncthreads();
    int i = rb + t;
    if (ct < (i >> 6)) return;
    float4 bi = g_obox[b][i];
    float ai = (bi.z - bi.x) * (bi.w - bi.y);
    u64 mask = 0ull;
    int jbase = ct * 64;
    #pragma unroll 8
    for (int j = 0; j < 64; j++) {
        float4 bj = cb[j];
        float w = fminf(bi.z, bj.z) - fmaxf(bi.x, bj.x);
        float h = fminf(bi.w, bj.w) - fmaxf(bi.y, bj.y);
        w = fmaxf(w, 0.0f); h = fmaxf(h, 0.0f);
        float inter = w * h;
        bool sup = (inter > NMS_TH * (ai + ca[j] - inter)) && (jbase + j > i);
        if (sup) mask |= (1ull << j);
    }
    g_sup[b][i][ct] = mask;
}

// Jacobi fixpoint NMS + top-100 emit + counter reset.
__global__ void k_nms_out(float* __restrict__ out, int B) {
    int b = blockIdx.x;
    int tid = threadIdx.x, lane = tid & 31, wid = tid >> 5;  // 32 warps
    __shared__ u64 sh_kept[32], sh_valid[32];
    __shared__ u64 part[32][33];
    __shared__ int sh_changed;

    {
        int s0 = wid * 64 + lane;
        u32 b0 = __ballot_sync(~0u, g_score[b][s0] > SCORE_TH);
        u32 b1 = __ballot_sync(~0u, g_score[b][s0 + 32] > SCORE_TH);
        if (lane == 0) {
            u64 v = ((u64)b1 << 32) | (u64)b0;
            sh_valid[wid] = v;
            sh_kept[wid] = v;
        }
    }
    __syncthreads();

    while (true) {
        u64 acc = 0ull;
        for (int r = wid; r < KPRE; r += 32) {
            if (((sh_kept[r >> 6] >> (r & 63)) & 1ull) && ((r >> 6) <= lane))
                acc |= g_sup[b][r][lane];
        }
        part[wid][lane] = acc;
        if (tid == 0) sh_changed = 0;
        __syncthreads();
        u64 v = part[lane][wid];
        #pragma unroll
        for (int o = 16; o; o >>= 1) v |= __shfl_xor_sync(~0u, v, o);
        u64 oldk = sh_kept[wid];
        u64 nk = sh_valid[wid] & ~v;
        __syncthreads();
        if (lane == 0) {
            sh_kept[wid] = nk;
            if (nk != oldk) sh_changed = 1;
        }
        __syncthreads();
        if (!sh_changed) break;
    }

    const int soff = B * DETS * 4;
    const int loff = B * DETS * 4 + B * DETS;
    for (int i = tid; i < DETS; i += 1024) {
        float* bo = out + (size_t)(b * DETS + i) * 4;
        bo[0] = 0.f; bo[1] = 0.f; bo[2] = 0.f; bo[3] = 0.f;
        out[soff + b * DETS + i] = 0.f;
        out[loff + b * DETS + i] = -1.f;
    }
    __syncthreads();

    if (wid == 0) {
        int base = 0;
        for (int w = 0; w < 32 && base < DETS; w++) {
            u64 word = sh_kept[w];
            u32 lo = (u32)word;
            u32 hi = (u32)(word >> 32);
            {
                u32 myb = (lo >> lane) & 1u;
                int pre = __popc(lo & ((1u << lane) - 1u));
                int rank = base + pre;
                if (myb && rank < DETS) {
                    int s = w * 64 + lane;
                    float4 bx = g_box[b][s];
                    float* bo = out + (size_t)(b * DETS + rank) * 4;
                    bo[0] = bx.x; bo[1] = bx.y; bo[2] = bx.z; bo[3] = bx.w;
                    out[soff + b * DETS + rank] = g_score[b][s];
                    out[loff + b * DETS + rank] = (float)g_label[b][s];
                }
                base += __popc(lo);
            }
            {
                u32 myb = (hi >> lane) & 1u;
                int pre = __popc(hi & ((1u << lane) - 1u));
                int rank = base + pre;
                if (myb && rank < DETS) {
                    int s = w * 64 + 32 + lane;
                    float4 bx = g_box[b][s];
                    float* bo = out + (size_t)(b * DETS + rank) * 4;
                    bo[0] = bx.x; bo[1] = bx.y; bo[2] = bx.z; bo[3] = bx.w;
                    out[soff + b * DETS + rank] = g_score[b][s];
                    out[loff + b * DETS + rank] = (float)g_label[b][s];
                }
                base += __popc(hi);
            }
        }
    }
    // reset candidate counter for next invocation (statics start zeroed)
    if (tid == 0) g_cnt[b] = 0;
}

extern "C" void kernel_launch(void* const* d_in, const int* in_sizes, int n_in,
                              void* d_out, int out_size) {
    const float* logits = (const float*)d_in[0];
    const float* reg = (const float*)d_in[1];
    const float* props = (const float*)d_in[2];
    const void* p_h = d_in[3];
    const void* p_w = d_in[4];
    float* out = (float*)d_out;

    int B = in_sizes[0] / (NPROP * NCLS);
    if (B < 1) B = 1;
    if (B > BMAX) B = BMAX;

    static bool attr_done = false;
    cudaFuncSetAttribute(k_select, cudaFuncAttributeMaxDynamicSharedMemorySize,
                         SHCAP * (int)sizeof(u64));
    (void)attr_done;

    int rows = B * NPROP;
    k_cand<<<(rows + 7) / 8, 256>>>(logits, reg, props, p_h, p_w, B);
    k_select<<<B, 1024, SHCAP * sizeof(u64)>>>(reg, props, p_h, p_w, B);
    dim3 gs(KPRE / 64, KPRE / 256, B);
    k_sup<<<gs, 256>>>(B);
    k_nms_out<<<B, 1024>>>(out, B);
}